// round 5
// baseline (speedup 1.0000x reference)
#include <cuda_runtime.h>

#define NN 2048
#define BB 4
#define THREADS 128
#define ROWS_PER_BLOCK 8                         // 2 row-groups x 4 rows
#define BLOCKS_PER_BATCH (NN / ROWS_PER_BLOCK)   // 256
#define CHUNK 512
#define NCHUNKS (NN / CHUNK)                     // 4
#define PCHUNK (CHUNK + CHUNK / 8)               // padded: j + (j>>3) -> 576

typedef unsigned long long u64;

// Scratch: sin/cos of theta, float4 per (b, n)  (AoS: [d0 d1 d2 d3])
__device__ float4 g_s[BB * NN];
__device__ float4 g_c[BB * NN];

__global__ void sincos_kernel(const float4* __restrict__ theta) {
    int idx = blockIdx.x * blockDim.x + threadIdx.x;
    if (idx >= BB * NN) return;
    float4 t = theta[idx];
    float4 s, c;
    __sincosf(t.x, &s.x, &c.x);
    __sincosf(t.y, &s.y, &c.y);
    __sincosf(t.z, &s.z, &c.z);
    __sincosf(t.w, &s.w, &c.w);
    g_s[idx] = s;
    g_c[idx] = c;
}

__device__ __forceinline__ void fma2(u64& d, u64 a, u64 b) {
    asm("fma.rn.f32x2 %0, %1, %2, %0;" : "+l"(d) : "l"(a), "l"(b));
}
__device__ __forceinline__ u64 pack2(float lo, float hi) {
    u64 r;
    asm("mov.b64 %0, {%1, %2};" : "=l"(r) : "f"(lo), "f"(hi));
    return r;
}
__device__ __forceinline__ void unpack2(float& lo, float& hi, u64 v) {
    asm("mov.b64 {%0, %1}, %2;" : "=f"(lo), "=f"(hi) : "l"(v));
}
__device__ __forceinline__ u64 add2(u64 a, u64 b) {
    u64 r;
    asm("add.rn.f32x2 %0, %1, %2;" : "=l"(r) : "l"(a), "l"(b));
    return r;
}

__global__ __launch_bounds__(THREADS, 7)
void kuramoto_kernel(const float* __restrict__ W,
                     const float* __restrict__ alpha,
                     const float4* __restrict__ gamma,
                     float4* __restrict__ out) {
    __shared__ float4 s_sh[PCHUNK];          // 9216 B (padded)
    __shared__ float4 c_sh[PCHUNK];          // 9216 B
    __shared__ u64 red[4][4][4];             // [warp][r][P01,P23,Q01,Q23]

    const int b    = blockIdx.x / BLOCKS_PER_BATCH;
    const int row0 = (blockIdx.x % BLOCKS_PER_BATCH) * ROWS_PER_BLOCK;
    const int base = b * NN;

    const int warp   = threadIdx.x >> 5;
    const int lane   = threadIdx.x & 31;
    const int r      = lane >> 3;            // row within 4-row group
    const int jx     = lane & 7;             // 8 j-slots per row
    const int rowgrp = warp >> 1;            // warps {0,1}->grp0, {2,3}->grp1
    const int jhalf  = warp & 1;             // j half of each chunk
    const int i      = row0 + rowgrp * 4 + r;    // this lane's row

    // Row base ONLY — the j offset comes exclusively from jloc below.
    const float* __restrict__ Wr = W     + (size_t)(base + i) * NN;
    const float* __restrict__ Ar = alpha + (size_t)(base + i) * NN;

    u64 P01 = 0, P23 = 0, Q01 = 0, Q23 = 0;

    for (int ch = 0; ch < NCHUNKS; ++ch) {
        __syncthreads();
        // Cooperative padded load of this chunk's sin/cos table
        #pragma unroll
        for (int t = 0; t < CHUNK; t += THREADS) {
            int idx = t + threadIdx.x;
            int p   = idx + (idx >> 3);
            s_sh[p] = g_s[base + ch * CHUNK + idx];
            c_sh[p] = g_c[base + ch * CHUNK + idx];
        }
        __syncthreads();

        const int chbase = ch * CHUNK;

        #pragma unroll 2
        for (int it = 0; it < CHUNK / 2 / 32; ++it) {    // 8 iters of 32 j
            const int jloc = jhalf * (CHUNK / 2) + it * 32 + 4 * jx; // chunk-local j
            const float4 W4 = __ldg((const float4*)(Wr + chbase + jloc));
            const float4 A4 = __ldg((const float4*)(Ar + chbase + jloc));
            const int pbase = jloc + (jloc >> 3);   // (jloc+m)>>3 == jloc>>3 for m<4

            #pragma unroll
            for (int m = 0; m < 4; ++m) {
                const ulonglong2 sp = *reinterpret_cast<const ulonglong2*>(&s_sh[pbase + m]);
                const ulonglong2 cp = *reinterpret_cast<const ulonglong2*>(&c_sh[pbase + m]);
                const float w = (&W4.x)[m];
                float sa, ca;
                __sincosf((&A4.x)[m], &sa, &ca);
                const float Av = w * ca;            // W * cos(alpha)
                const float Bv = w * sa;            // W * sin(alpha)
                const u64 Av2  = pack2(Av, Av);
                const u64 Bv2  = pack2(Bv, Bv);
                const u64 nBv2 = pack2(-Bv, -Bv);
                // P += Av*c + Bv*s ;  Q += Av*s - Bv*c   (packed d-pairs)
                fma2(P01, Av2, cp.x);  fma2(P01, Bv2, sp.x);
                fma2(P23, Av2, cp.y);  fma2(P23, Bv2, sp.y);
                fma2(Q01, Av2, sp.x);  fma2(Q01, nBv2, cp.x);
                fma2(Q23, Av2, sp.y);  fma2(Q23, nBv2, cp.y);
            }
        }
    }

    // Reduce across jx (8 lanes per row) within the warp
    #pragma unroll
    for (int off = 1; off < 8; off <<= 1) {
        P01 = add2(P01, __shfl_xor_sync(0xffffffffu, P01, off));
        P23 = add2(P23, __shfl_xor_sync(0xffffffffu, P23, off));
        Q01 = add2(Q01, __shfl_xor_sync(0xffffffffu, Q01, off));
        Q23 = add2(Q23, __shfl_xor_sync(0xffffffffu, Q23, off));
    }

    // Publish warp partials, combine the j-half warp pairs
    if (jx == 0) {
        red[warp][r][0] = P01;  red[warp][r][1] = P23;
        red[warp][r][2] = Q01;  red[warp][r][3] = Q23;
    }
    __syncthreads();

    if (jhalf == 0 && jx == 0) {
        const u64 p01 = add2(red[warp][r][0], red[warp + 1][r][0]);
        const u64 p23 = add2(red[warp][r][1], red[warp + 1][r][1]);
        const u64 q01 = add2(red[warp][r][2], red[warp + 1][r][2]);
        const u64 q23 = add2(red[warp][r][3], red[warp + 1][r][3]);

        float P0, P1, P2, P3, Q0, Q1, Q2, Q3;
        unpack2(P0, P1, p01); unpack2(P2, P3, p23);
        unpack2(Q0, Q1, q01); unpack2(Q2, Q3, q23);

        const float invn = 1.0f / (float)NN;     // COUPLING / N
        float4 g  = gamma[base + i];
        float4 si = g_s[base + i];
        float4 ci = g_c[base + i];

        // theta_next = gamma + (1/N)(c_i*Q - s_i*P)   (theta cancels, DT=ATTR=1)
        float n0 = g.x + invn * (ci.x * Q0 - si.x * P0);
        float n1 = g.y + invn * (ci.y * Q1 - si.y * P1);
        float n2 = g.z + invn * (ci.z * Q2 - si.z * P2);
        float n3 = g.w + invn * (ci.w * Q3 - si.w * P3);

        float nrm = sqrtf(n0 * n0 + n1 * n1 + n2 * n2 + n3 * n3);
        float inv = 1.0f / fmaxf(nrm, 1e-6f);
        out[base + i] = make_float4(n0 * inv, n1 * inv, n2 * inv, n3 * inv);
    }
}

extern "C" void kernel_launch(void* const* d_in, const int* in_sizes, int n_in,
                              void* d_out, int out_size) {
    const float* theta = (const float*)d_in[0];   // [B, N, 4]
    const float* gamma = (const float*)d_in[1];   // [B, N, 4]
    const float* W     = (const float*)d_in[2];   // [B, N, N]
    const float* alpha = (const float*)d_in[3];   // [B, N, N]
    float* out = (float*)d_out;                   // [B, N, 4]

    sincos_kernel<<<(BB * NN + 255) / 256, 256>>>((const float4*)theta);

    // 1024 blocks x 128 threads: 8 rows/block, 4-row warp tiles,
    // broadcast LDS with anti-conflict padding, single wave at 7 CTAs/SM.
    kuramoto_kernel<<<BB * BLOCKS_PER_BATCH, THREADS>>>(
        W, alpha, (const float4*)gamma, (float4*)out);
}

// round 6
// speedup vs baseline: 1.1107x; 1.1107x over previous
#include <cuda_runtime.h>

#define NN 2048
#define BB 4
#define THREADS 128
#define ROWS_PER_BLOCK 8                         // 2 row-groups x 4 rows
#define BLOCKS_PER_BATCH (NN / ROWS_PER_BLOCK)   // 256
#define CHUNK 512
#define NCHUNKS (NN / CHUNK)                     // 4
#define PCHUNK (CHUNK + CHUNK / 8)               // padded: j + (j>>3) -> 576

typedef unsigned long long u64;

__device__ __forceinline__ void fma2(u64& d, u64 a, u64 b) {
    asm("fma.rn.f32x2 %0, %1, %2, %0;" : "+l"(d) : "l"(a), "l"(b));
}
__device__ __forceinline__ u64 pack2(float lo, float hi) {
    u64 r;
    asm("mov.b64 %0, {%1, %2};" : "=l"(r) : "f"(lo), "f"(hi));
    return r;
}
__device__ __forceinline__ void unpack2(float& lo, float& hi, u64 v) {
    asm("mov.b64 {%0, %1}, %2;" : "=f"(lo), "=f"(hi) : "l"(v));
}
__device__ __forceinline__ u64 add2(u64 a, u64 b) {
    u64 r;
    asm("add.rn.f32x2 %0, %1, %2;" : "=l"(r) : "l"(a), "l"(b));
    return r;
}

__global__ __launch_bounds__(THREADS, 7)
void kuramoto_kernel(const float* __restrict__ W,
                     const float* __restrict__ alpha,
                     const float4* __restrict__ theta,
                     const float4* __restrict__ gamma,
                     float4* __restrict__ out) {
    __shared__ float4 s_sh[PCHUNK];          // 9216 B (padded)
    __shared__ float4 c_sh[PCHUNK];          // 9216 B
    __shared__ u64 red[4][4][4];             // [warp][r][P01,P23,Q01,Q23]

    const int b    = blockIdx.x / BLOCKS_PER_BATCH;
    const int row0 = (blockIdx.x % BLOCKS_PER_BATCH) * ROWS_PER_BLOCK;
    const int base = b * NN;

    const int warp   = threadIdx.x >> 5;
    const int lane   = threadIdx.x & 31;
    const int r      = lane >> 3;            // row within 4-row group
    const int jx     = lane & 7;             // 8 j-slots per row
    const int rowgrp = warp >> 1;            // warps {0,1}->grp0, {2,3}->grp1
    const int jhalf  = warp & 1;             // j half of each chunk
    const int i      = row0 + rowgrp * 4 + r;    // this lane's row

    // Row base ONLY — the j offset comes exclusively from jloc below.
    const float* __restrict__ Wr = W     + (size_t)(base + i) * NN;
    const float* __restrict__ Ar = alpha + (size_t)(base + i) * NN;

    u64 P01 = 0, P23 = 0, Q01 = 0, Q23 = 0;

    for (int ch = 0; ch < NCHUNKS; ++ch) {
        __syncthreads();
        // Build this chunk's sin/cos table IN-KERNEL from theta (8 KB read,
        // L2-resident; no scratch kernel, no global round-trip).
        #pragma unroll
        for (int t = 0; t < CHUNK; t += THREADS) {
            const int idx = t + threadIdx.x;
            const float4 th = theta[base + ch * CHUNK + idx];
            float4 s, c;
            __sincosf(th.x, &s.x, &c.x);
            __sincosf(th.y, &s.y, &c.y);
            __sincosf(th.z, &s.z, &c.z);
            __sincosf(th.w, &s.w, &c.w);
            const int p = idx + (idx >> 3);
            s_sh[p] = s;
            c_sh[p] = c;
        }
        __syncthreads();

        const int chbase = ch * CHUNK;

        #pragma unroll 2
        for (int it = 0; it < CHUNK / 2 / 32; ++it) {    // 8 iters of 32 j
            const int jloc = jhalf * (CHUNK / 2) + it * 32 + 4 * jx; // chunk-local j
            const float4 W4 = __ldg((const float4*)(Wr + chbase + jloc));
            const float4 A4 = __ldg((const float4*)(Ar + chbase + jloc));
            const int pbase = jloc + (jloc >> 3);   // (jloc+m)>>3 == jloc>>3 for m<4

            #pragma unroll
            for (int m = 0; m < 4; ++m) {
                const ulonglong2 sp = *reinterpret_cast<const ulonglong2*>(&s_sh[pbase + m]);
                const ulonglong2 cp = *reinterpret_cast<const ulonglong2*>(&c_sh[pbase + m]);
                const float w = (&W4.x)[m];
                float sa, ca;
                __sincosf((&A4.x)[m], &sa, &ca);
                const float Av = w * ca;            // W * cos(alpha)
                const float Bv = w * sa;            // W * sin(alpha)
                const u64 Av2  = pack2(Av, Av);
                const u64 Bv2  = pack2(Bv, Bv);
                const u64 nBv2 = pack2(-Bv, -Bv);
                // P += Av*c + Bv*s ;  Q += Av*s - Bv*c   (packed d-pairs)
                fma2(P01, Av2, cp.x);  fma2(P01, Bv2, sp.x);
                fma2(P23, Av2, cp.y);  fma2(P23, Bv2, sp.y);
                fma2(Q01, Av2, sp.x);  fma2(Q01, nBv2, cp.x);
                fma2(Q23, Av2, sp.y);  fma2(Q23, nBv2, cp.y);
            }
        }
    }

    // Reduce across jx (8 lanes per row) within the warp
    #pragma unroll
    for (int off = 1; off < 8; off <<= 1) {
        P01 = add2(P01, __shfl_xor_sync(0xffffffffu, P01, off));
        P23 = add2(P23, __shfl_xor_sync(0xffffffffu, P23, off));
        Q01 = add2(Q01, __shfl_xor_sync(0xffffffffu, Q01, off));
        Q23 = add2(Q23, __shfl_xor_sync(0xffffffffu, Q23, off));
    }

    // Publish warp partials, combine the j-half warp pairs
    if (jx == 0) {
        red[warp][r][0] = P01;  red[warp][r][1] = P23;
        red[warp][r][2] = Q01;  red[warp][r][3] = Q23;
    }
    __syncthreads();

    if (jhalf == 0 && jx == 0) {
        const u64 p01 = add2(red[warp][r][0], red[warp + 1][r][0]);
        const u64 p23 = add2(red[warp][r][1], red[warp + 1][r][1]);
        const u64 q01 = add2(red[warp][r][2], red[warp + 1][r][2]);
        const u64 q23 = add2(red[warp][r][3], red[warp + 1][r][3]);

        float P0, P1, P2, P3, Q0, Q1, Q2, Q3;
        unpack2(P0, P1, p01); unpack2(P2, P3, p23);
        unpack2(Q0, Q1, q01); unpack2(Q2, Q3, q23);

        const float invn = 1.0f / (float)NN;     // COUPLING / N
        const float4 g  = gamma[base + i];
        const float4 th = theta[base + i];
        float4 si, ci;
        __sincosf(th.x, &si.x, &ci.x);
        __sincosf(th.y, &si.y, &ci.y);
        __sincosf(th.z, &si.z, &ci.z);
        __sincosf(th.w, &si.w, &ci.w);

        // theta_next = gamma + (1/N)(c_i*Q - s_i*P)   (theta cancels, DT=ATTR=1)
        float n0 = g.x + invn * (ci.x * Q0 - si.x * P0);
        float n1 = g.y + invn * (ci.y * Q1 - si.y * P1);
        float n2 = g.z + invn * (ci.z * Q2 - si.z * P2);
        float n3 = g.w + invn * (ci.w * Q3 - si.w * P3);

        float nrm = sqrtf(n0 * n0 + n1 * n1 + n2 * n2 + n3 * n3);
        float inv = 1.0f / fmaxf(nrm, 1e-6f);
        out[base + i] = make_float4(n0 * inv, n1 * inv, n2 * inv, n3 * inv);
    }
}

extern "C" void kernel_launch(void* const* d_in, const int* in_sizes, int n_in,
                              void* d_out, int out_size) {
    const float* theta = (const float*)d_in[0];   // [B, N, 4]
    const float* gamma = (const float*)d_in[1];   // [B, N, 4]
    const float* W     = (const float*)d_in[2];   // [B, N, N]
    const float* alpha = (const float*)d_in[3];   // [B, N, N]
    float* out = (float*)d_out;                   // [B, N, 4]

    // Single fused kernel: 1024 blocks x 128 threads, in-block sincos table,
    // broadcast LDS, packed f32x2 FMAs, single wave at 7 CTAs/SM.
    kuramoto_kernel<<<BB * BLOCKS_PER_BATCH, THREADS>>>(
        W, alpha, (const float4*)theta, (const float4*)gamma, (float4*)out);
}